// round 13
// baseline (speedup 1.0000x reference)
#include <cuda_runtime.h>
#include <cuda_bf16.h>
#include <cstdint>

#define N_NODES 50000
#define N_GRAPHS 128
#define DH 64
#define DOUT 16
#define N_EDGES 1250000
#define CAP 128                       // padded slots per node (deg = 25±5)

// -------- static device scratch --------
__device__ uint4 g_xb[(size_t)N_NODES * 8];    // bf16 shadow (128B/row)
__device__ uint4 g_h1b[(size_t)N_NODES * 8];
__device__ uint4 g_h2b[(size_t)N_NODES * 8];
__device__ int   g_deg[N_NODES];
__device__ int   g_csrp[(size_t)N_NODES * CAP + 256];
__device__ float g_P1[N_GRAPHS * DH];
__device__ float g_P2[N_GRAPHS * DH];
__device__ int   g_nb[N_GRAPHS + 1];

// unpack 8 bf16 (uint4) and accumulate into 8 fp32 (shift = exact bf16->f32)
#define ACC8(v)                                                         \
    do {                                                                \
        a0 += __uint_as_float((v).x << 16);                             \
        a1 += __uint_as_float((v).x & 0xffff0000u);                     \
        a2 += __uint_as_float((v).y << 16);                             \
        a3 += __uint_as_float((v).y & 0xffff0000u);                     \
        a4 += __uint_as_float((v).z << 16);                             \
        a5 += __uint_as_float((v).z & 0xffff0000u);                     \
        a6 += __uint_as_float((v).w << 16);                             \
        a7 += __uint_as_float((v).w & 0xffff0000u);                     \
    } while (0)

__device__ __forceinline__ uint32_t su32(const void* p) {
    return (uint32_t)__cvta_generic_to_shared(p);
}
__device__ __forceinline__ uint32_t pack_bf16x2(float lo, float hi) {
    uint32_t r;
    asm("cvt.rn.bf16x2.f32 %0, %1, %2;" : "=r"(r) : "f"(hi), "f"(lo));
    return r;
}
// m16n8k16 bf16 HMMA, fp32 accumulate
#define MMA16816(c, a0, a1, a2, a3, b0, b1)                                   \
    asm volatile(                                                             \
        "mma.sync.aligned.m16n8k16.row.col.f32.bf16.bf16.f32 "                \
        "{%0,%1,%2,%3}, {%4,%5,%6,%7}, {%8,%9}, {%0,%1,%2,%3};"               \
        : "+f"((c)[0]), "+f"((c)[1]), "+f"((c)[2]), "+f"((c)[3])              \
        : "r"(a0), "r"(a1), "r"(a2), "r"(a3), "r"(b0), "r"(b1))

// ---------------- build: hist writes padded CSR directly + bounds + x->bf16 ----------------
__global__ void hist_k(const int* __restrict__ ei, int ne,
                       int* __restrict__ deg,
                       int* __restrict__ csrp,
                       const int* __restrict__ batch,
                       int* __restrict__ nb,
                       const float* __restrict__ x,
                       __nv_bfloat162* __restrict__ xb) {
    int t = blockIdx.x * blockDim.x + threadIdx.x;
    if (t < ne) {
        int d = __ldg(&ei[ne + t]);
        int s = __ldg(&ei[t]);
        int r = atomicAdd(&deg[d], 1);
        if (r < CAP) csrp[(size_t)d * CAP + r] = s;
    }
    if (t < N_NODES) {
        int b = __ldg(&batch[t]);
        if (t == 0) {
            for (int g = 0; g <= b; ++g) nb[g] = 0;
        } else {
            int p = __ldg(&batch[t - 1]);
            for (int g = p + 1; g <= b; ++g) nb[g] = t;
        }
        if (t == N_NODES - 1) {
            for (int g = b + 1; g <= N_GRAPHS; ++g) nb[g] = N_NODES;
        }
    }
    const float2* x2 = (const float2*)x;
    int stride = gridDim.x * blockDim.x;
    for (int i = t; i < N_NODES * DH / 2; i += stride) {
        float2 v = __ldg(&x2[i]);
        xb[i] = __float22bfloat162_rn(v);
    }
}

// ------- fused layer: bf16 gather (padded CSR, R12 batch structure) + HMMA -------
#define A_STRIDE 272
#define A_BYTES (128 * A_STRIDE)
#define B_BYTES (64 * A_STRIDE)
#define LAYER_SMEM (A_BYTES + 2 * B_BYTES)   // 69632

__global__ __launch_bounds__(256, 3)
void layer_k(const uint4* __restrict__ Xb,
             const int* __restrict__ csrp,
             const int* __restrict__ deg,
             const float* __restrict__ Wrel,
             const float* __restrict__ brel,
             const float* __restrict__ Wroot,
             uint32_t* __restrict__ outb,
             int do_relu) {
    extern __shared__ char sm[];
    __shared__ float s_bias[64];

    const unsigned FULL = 0xffffffffu;
    int tid = threadIdx.x;
    int warp = tid >> 5, lane = tid & 31;
    int rowBase = blockIdx.x * 128;

    uint32_t smA = su32(sm);
    uint32_t smBhi = smA + A_BYTES;
    uint32_t smBlo = smBhi + B_BYTES;

    if (tid < 64) s_bias[tid] = __ldg(&brel[tid]);

    // W stacked [Wrel;Wroot] -> Bt[n][k] hi/lo bf16
    for (int i = tid; i < 8192; i += 256) {
        int k = i >> 6, n = i & 63;
        float w = (k < 64) ? __ldg(&Wrel[k * 64 + n]) : __ldg(&Wroot[(k - 64) * 64 + n]);
        __nv_bfloat16 hi = __float2bfloat16_rn(w);
        __nv_bfloat16 lo = __float2bfloat16_rn(w - __bfloat162float(hi));
        uint32_t off = (uint32_t)(n * A_STRIDE + k * 2);
        asm volatile("st.shared.b16 [%0], %1;" :: "r"(smBhi + off), "h"(__bfloat16_as_ushort(hi)));
        asm volatile("st.shared.b16 [%0], %1;" :: "r"(smBlo + off), "h"(__bfloat16_as_ushort(lo)));
    }

    // x rows (bf16) -> A right half (cols 64..127)
    for (int i = tid; i < 1024; i += 256) {
        int r = i >> 3, c = i & 7;
        int g = rowBase + r;
        uint4 v = (g < N_NODES) ? __ldg(&Xb[(size_t)g * 8 + c])
                                : make_uint4(0, 0, 0, 0);
        uint32_t off = (uint32_t)(r * A_STRIDE + 128 + c * 16);
        asm volatile("st.shared.v4.b32 [%0], {%1,%2,%3,%4};"
                     :: "r"(smA + off), "r"(v.x), "r"(v.y), "r"(v.z), "r"(v.w));
    }

    // gather: 16 rows/warp -> A left half (R12 structure, fixed-stride rows)
    {
        int h = lane >> 3;
        int c = lane & 7;
        int rbase = rowBase + warp * 16;

        int dv = 0;
        if (lane < 16) {
            int idx = rbase + lane;
            if (idx < N_NODES) {
                dv = __ldg(&deg[idx]);
                if (dv > CAP) dv = CAP;
            }
        }
        // prefetch first 16 indices of first row
        int nxt = (lane < 16 && rbase < N_NODES)
                ? __ldg(&csrp[(size_t)rbase * CAP + lane]) : 0;

        #pragma unroll 1
        for (int rr = 0; rr < 16; ++rr) {
            int grow = rbase + rr;
            size_t ro = (size_t)grow * CAP;
            int degr = __shfl_sync(FULL, dv, rr);
            float a0 = 0.f, a1 = 0.f, a2 = 0.f, a3 = 0.f;
            float a4 = 0.f, a5 = 0.f, a6 = 0.f, a7 = 0.f;

            int j = 0;
            // main: 16-edge batches, 4 LDG.128 per BB, streamed idx prefetch
            #pragma unroll 1
            while (j + 16 <= degr) {
                int curI = nxt;
                nxt = (lane < 16) ? __ldg(&csrp[ro + j + 16 + lane]) : 0;
                int s0 = __shfl_sync(FULL, curI, 0 + h);
                int s1 = __shfl_sync(FULL, curI, 4 + h);
                int s2 = __shfl_sync(FULL, curI, 8 + h);
                int s3 = __shfl_sync(FULL, curI, 12 + h);
                uint4 v0 = __ldg(&Xb[(size_t)s0 * 8 + c]);
                uint4 v1 = __ldg(&Xb[(size_t)s1 * 8 + c]);
                uint4 v2 = __ldg(&Xb[(size_t)s2 * 8 + c]);
                uint4 v3 = __ldg(&Xb[(size_t)s3 * 8 + c]);
                ACC8(v0); ACC8(v1); ACC8(v2); ACC8(v3);
                j += 16;
            }
            int rem = degr - j;   // 0..15
            if (rem > 0) {
                int curI = nxt;
                int q0 = 0;
                if (rem >= 8) {
                    int sa = __shfl_sync(FULL, curI, 0 + h);
                    int sb2 = __shfl_sync(FULL, curI, 4 + h);
                    uint4 va = __ldg(&Xb[(size_t)sa * 8 + c]);
                    uint4 vb = __ldg(&Xb[(size_t)sb2 * 8 + c]);
                    ACC8(va); ACC8(vb);
                    q0 = 8;
                }
                #pragma unroll
                for (int q = 0; q < 16; q += 4) {
                    if (q < q0) continue;
                    if (q >= rem) break;
                    int e = q + h;
                    bool valid = e < rem;
                    int s = __shfl_sync(FULL, curI, valid ? e : 0);
                    uint4 v = __ldg(&Xb[(size_t)s * 8 + c]);
                    if (valid) { ACC8(v); }
                }
            }
            // prefetch first 16 indices of next row
            if (rr < 15) {
                int gn = grow + 1;
                nxt = (lane < 16 && gn < N_NODES)
                    ? __ldg(&csrp[(size_t)gn * CAP + lane]) : 0;
            }

            #pragma unroll
            for (int o = 8; o <= 16; o <<= 1) {
                a0 += __shfl_xor_sync(FULL, a0, o);
                a1 += __shfl_xor_sync(FULL, a1, o);
                a2 += __shfl_xor_sync(FULL, a2, o);
                a3 += __shfl_xor_sync(FULL, a3, o);
                a4 += __shfl_xor_sync(FULL, a4, o);
                a5 += __shfl_xor_sync(FULL, a5, o);
                a6 += __shfl_xor_sync(FULL, a6, o);
                a7 += __shfl_xor_sync(FULL, a7, o);
            }
            if (lane < 8) {
                int r = warp * 16 + rr;
                uint32_t p0 = pack_bf16x2(a0, a1);
                uint32_t p1 = pack_bf16x2(a2, a3);
                uint32_t p2 = pack_bf16x2(a4, a5);
                uint32_t p3 = pack_bf16x2(a6, a7);
                uint32_t off = (uint32_t)(r * A_STRIDE + c * 16);
                asm volatile("st.shared.v4.b32 [%0], {%1,%2,%3,%4};"
                             :: "r"(smA + off), "r"(p0), "r"(p1), "r"(p2), "r"(p3));
            }
        }
    }
    __syncthreads();

    // HMMA: warp computes rows [warp*16, +16) x 64 cols
    float acc[8][4] = {};
    {
        uint32_t aBase = smA + (uint32_t)((warp * 16 + (lane >> 2)) * A_STRIDE + (lane & 3) * 4);
        uint32_t bBase = (uint32_t)((lane >> 2) * A_STRIDE + (lane & 3) * 4);
        #pragma unroll
        for (int k = 0; k < 8; ++k) {
            uint32_t ak = aBase + k * 32;
            uint32_t a0, a1, a2, a3;
            asm volatile("ld.shared.b32 %0, [%1];" : "=r"(a0) : "r"(ak));
            asm volatile("ld.shared.b32 %0, [%1];" : "=r"(a1) : "r"(ak + 8 * A_STRIDE));
            asm volatile("ld.shared.b32 %0, [%1];" : "=r"(a2) : "r"(ak + 16));
            asm volatile("ld.shared.b32 %0, [%1];" : "=r"(a3) : "r"(ak + 8 * A_STRIDE + 16));
            #pragma unroll
            for (int nf = 0; nf < 8; ++nf) {
                uint32_t bk = bBase + nf * (8 * A_STRIDE) + k * 32;
                uint32_t b0, b1;
                asm volatile("ld.shared.b32 %0, [%1];" : "=r"(b0) : "r"(smBhi + bk));
                asm volatile("ld.shared.b32 %0, [%1];" : "=r"(b1) : "r"(smBhi + bk + 16));
                MMA16816(acc[nf], a0, a1, a2, a3, b0, b1);
                asm volatile("ld.shared.b32 %0, [%1];" : "=r"(b0) : "r"(smBlo + bk));
                asm volatile("ld.shared.b32 %0, [%1];" : "=r"(b1) : "r"(smBlo + bk + 16));
                MMA16816(acc[nf], a0, a1, a2, a3, b0, b1);
            }
        }
    }

    // epilogue: bias + relu, bf16 stores
    {
        int r0 = rowBase + warp * 16 + (lane >> 2);
        int r1 = r0 + 8;
        int colq = (lane & 3) * 2;
        #pragma unroll
        for (int nf = 0; nf < 8; ++nf) {
            int cc = nf * 8 + colq;
            float b0 = s_bias[cc], b1 = s_bias[cc + 1];
            float o0 = acc[nf][0] + b0, o1 = acc[nf][1] + b1;
            float o2 = acc[nf][2] + b0, o3 = acc[nf][3] + b1;
            if (do_relu) {
                o0 = fmaxf(o0, 0.f); o1 = fmaxf(o1, 0.f);
                o2 = fmaxf(o2, 0.f); o3 = fmaxf(o3, 0.f);
            }
            if (r0 < N_NODES) outb[(size_t)r0 * 32 + (cc >> 1)] = pack_bf16x2(o0, o1);
            if (r1 < N_NODES) outb[(size_t)r1 * 32 + (cc >> 1)] = pack_bf16x2(o2, o3);
        }
    }
}

// ---- P1[g] = sum over valid slots of graph g of h2b[src] (padded slot walk) ----
__global__ void p1_k(const uint4* __restrict__ Hb,
                     const int* __restrict__ csrp,
                     const int* __restrict__ deg,
                     const int* __restrict__ nb,
                     float* __restrict__ P1) {
    int g = blockIdx.x >> 2, part = blockIdx.x & 3;
    int ns = __ldg(&nb[g]), neE = __ldg(&nb[g + 1]);
    long long s0slot = (long long)ns * CAP;
    long long total = (long long)(neE - ns) * CAP;
    long long start = s0slot + ((total * part) >> 2);
    long long end = s0slot + ((total * (part + 1)) >> 2);
    int grp = threadIdx.x >> 3;   // 0..31 slot groups
    int c = threadIdx.x & 7;
    float a0 = 0.f, a1 = 0.f, a2 = 0.f, a3 = 0.f;
    float a4 = 0.f, a5 = 0.f, a6 = 0.f, a7 = 0.f;
    long long j = start + grp;
    // 4-deep unrolled slot walk (slots j, j+32, j+64, j+96)
    for (; j + 96 < end; j += 128) {
        #pragma unroll
        for (int u = 0; u < 4; ++u) {
            long long sl = j + u * 32;
            int node = (int)(sl >> 7);
            int r = (int)(sl & (CAP - 1));
            int dg = __ldg(&deg[node]);
            if (r < dg) {
                int s = __ldg(&csrp[sl]);
                uint4 v = __ldg(&Hb[(size_t)s * 8 + c]);
                ACC8(v);
            }
        }
    }
    for (; j < end; j += 32) {
        int node = (int)(j >> 7);
        int r = (int)(j & (CAP - 1));
        int dg = __ldg(&deg[node]);
        if (r < dg) {
            int s = __ldg(&csrp[j]);
            uint4 v = __ldg(&Hb[(size_t)s * 8 + c]);
            ACC8(v);
        }
    }
    __shared__ float sRed[32][72];
    *(float4*)&sRed[grp][c * 8]     = make_float4(a0, a1, a2, a3);
    *(float4*)&sRed[grp][c * 8 + 4] = make_float4(a4, a5, a6, a7);
    __syncthreads();
    if (threadIdx.x < 16) {
        int q = threadIdx.x;
        float4 s = make_float4(0.f, 0.f, 0.f, 0.f);
        #pragma unroll
        for (int t = 0; t < 32; ++t) {
            float4 v = *(float4*)&sRed[t][q * 4];
            s.x += v.x; s.y += v.y; s.z += v.z; s.w += v.w;
        }
        float* dst = P1 + g * DH + q * 4;
        asm volatile("red.global.add.v4.f32 [%0], {%1,%2,%3,%4};"
                     :: "l"(dst), "f"(s.x), "f"(s.y), "f"(s.z), "f"(s.w)
                     : "memory");
    }
}

// ---- P2[g] = sum over nodes of graph g of h2b (bf16 reads, fp32 acc) ----
__global__ void pool2_k(const uint4* __restrict__ Hb,
                        const int* __restrict__ nb,
                        float* __restrict__ P2) {
    int g = blockIdx.x;
    int s = __ldg(&nb[g]), e = __ldg(&nb[g + 1]);
    int grp = threadIdx.x >> 3;
    int c = threadIdx.x & 7;
    float a0 = 0.f, a1 = 0.f, a2 = 0.f, a3 = 0.f;
    float a4 = 0.f, a5 = 0.f, a6 = 0.f, a7 = 0.f;
    for (int r = s + grp; r < e; r += 32) {
        uint4 v = __ldg(&Hb[(size_t)r * 8 + c]);
        ACC8(v);
    }
    __shared__ float sRed[32][72];
    *(float4*)&sRed[grp][c * 8]     = make_float4(a0, a1, a2, a3);
    *(float4*)&sRed[grp][c * 8 + 4] = make_float4(a4, a5, a6, a7);
    __syncthreads();
    if (threadIdx.x < 16) {
        int q = threadIdx.x;
        float4 sv = make_float4(0.f, 0.f, 0.f, 0.f);
        #pragma unroll
        for (int t = 0; t < 32; ++t) {
            float4 v = *(float4*)&sRed[t][q * 4];
            sv.x += v.x; sv.y += v.y; sv.z += v.z; sv.w += v.w;
        }
        *(float4*)&P2[g * DH + q * 4] = sv;
    }
}

// ---- finale ----
__global__ void finale_k(const float* __restrict__ P1,
                         const float* __restrict__ P2,
                         const int* __restrict__ nb,
                         const float* __restrict__ Wrel,
                         const float* __restrict__ brel,
                         const float* __restrict__ Wroot,
                         const float* __restrict__ Wlin,
                         const float* __restrict__ blin,
                         float* __restrict__ out) {
    int g = blockIdx.x;
    int c = threadIdx.x;
    __shared__ float st[64];
    float cnt = fmaxf((float)(nb[g + 1] - nb[g]), 1.0f);
    float t = 0.f;
    #pragma unroll 8
    for (int k = 0; k < 64; ++k)
        t += P1[g * DH + k] * Wrel[k * DH + c] + P2[g * DH + k] * Wroot[k * DH + c];
    st[c] = t / cnt + brel[c];
    __syncthreads();
    if (c < DOUT) {
        float o = blin[c];
        #pragma unroll 8
        for (int k = 0; k < 64; ++k)
            o += st[k] * Wlin[k * DOUT + c];
        out[g * DOUT + c] = o;
    }
}

extern "C" void kernel_launch(void* const* d_in, const int* in_sizes, int n_in,
                              void* d_out, int out_size) {
    const float* x      = (const float*)d_in[0];
    const int*   ei     = (const int*)d_in[1];
    const int*   batch  = (const int*)d_in[3];
    const float* Wrel1  = (const float*)d_in[4];
    const float* brel1  = (const float*)d_in[5];
    const float* Wroot1 = (const float*)d_in[6];
    const float* Wrel2  = (const float*)d_in[7];
    const float* brel2  = (const float*)d_in[8];
    const float* Wroot2 = (const float*)d_in[9];
    const float* Wrel3  = (const float*)d_in[10];
    const float* brel3  = (const float*)d_in[11];
    const float* Wroot3 = (const float*)d_in[12];
    const float* Wlin   = (const float*)d_in[13];
    const float* blin   = (const float*)d_in[14];
    float* out = (float*)d_out;

    int ne = in_sizes[1] / 2;

    void *xb_p, *h1b_p, *h2b_p, *deg_p, *csrp_p, *p1_p, *p2_p, *nb_p;
    cudaGetSymbolAddress(&xb_p, g_xb);
    cudaGetSymbolAddress(&h1b_p, g_h1b);
    cudaGetSymbolAddress(&h2b_p, g_h2b);
    cudaGetSymbolAddress(&deg_p, g_deg);
    cudaGetSymbolAddress(&csrp_p, g_csrp);
    cudaGetSymbolAddress(&p1_p, g_P1);
    cudaGetSymbolAddress(&p2_p, g_P2);
    cudaGetSymbolAddress(&nb_p, g_nb);

    uint4* xb = (uint4*)xb_p;
    uint4* h1b = (uint4*)h1b_p;
    uint4* h2b = (uint4*)h2b_p;
    int* deg = (int*)deg_p;
    int* csrp = (int*)csrp_p;
    float* P1 = (float*)p1_p;
    float* P2 = (float*)p2_p;
    int* nb = (int*)nb_p;

    static int attr_set = 0;
    if (!attr_set) {
        cudaFuncSetAttribute(layer_k,
                             cudaFuncAttributeMaxDynamicSharedMemorySize, LAYER_SMEM);
        attr_set = 1;
    }

    int edgeBlocks = (ne + 255) / 256;
    int layerBlocks = (N_NODES + 127) / 128;   // 391

    cudaMemsetAsync(deg, 0, N_NODES * sizeof(int), 0);
    cudaMemsetAsync(P1, 0, N_GRAPHS * DH * sizeof(float), 0);

    hist_k<<<edgeBlocks, 256>>>(ei, ne, deg, csrp, batch, nb, x,
                                (__nv_bfloat162*)xb);

    layer_k<<<layerBlocks, 256, LAYER_SMEM>>>(xb,  csrp, deg, Wrel1, brel1, Wroot1,
                                              (uint32_t*)h1b, 1);
    layer_k<<<layerBlocks, 256, LAYER_SMEM>>>(h1b, csrp, deg, Wrel2, brel2, Wroot2,
                                              (uint32_t*)h2b, 1);

    p1_k<<<N_GRAPHS * 4, 256>>>(h2b, csrp, deg, nb, P1);
    pool2_k<<<N_GRAPHS, 256>>>(h2b, nb, P2);
    finale_k<<<N_GRAPHS, 64>>>(P1, P2, nb, Wrel3, brel3, Wroot3, Wlin, blin, out);
}

// round 14
// speedup vs baseline: 1.3344x; 1.3344x over previous
#include <cuda_runtime.h>
#include <cuda_bf16.h>
#include <cstdint>

#define N_NODES 50000
#define N_GRAPHS 128
#define DH 64
#define DOUT 16
#define SCAN_BLOCKS 49
#define N_EDGES 1250000

// -------- static device scratch --------
__device__ uint4 g_xb[(size_t)N_NODES * 8];    // bf16 shadow (128B/row)
__device__ uint4 g_h1b[(size_t)N_NODES * 8];
__device__ uint4 g_h2b[(size_t)N_NODES * 8];
__device__ int   g_deg[N_NODES];
__device__ int   g_roff[N_NODES + 1];
__device__ int   g_dr[N_EDGES];                // packed dst | (rank<<16)
__device__ int   g_csr[N_EDGES + 32];
__device__ float g_P1[N_GRAPHS * DH];
__device__ int   g_nb[N_GRAPHS + 1];
__device__ int   g_bsum[SCAN_BLOCKS];

// unpack 8 bf16 (uint4) and accumulate into 8 fp32 (shift = exact bf16->f32)
#define ACC8(v)                                                         \
    do {                                                                \
        a0 += __uint_as_float((v).x << 16);                             \
        a1 += __uint_as_float((v).x & 0xffff0000u);                     \
        a2 += __uint_as_float((v).y << 16);                             \
        a3 += __uint_as_float((v).y & 0xffff0000u);                     \
        a4 += __uint_as_float((v).z << 16);                             \
        a5 += __uint_as_float((v).z & 0xffff0000u);                     \
        a6 += __uint_as_float((v).w << 16);                             \
        a7 += __uint_as_float((v).w & 0xffff0000u);                     \
    } while (0)

__device__ __forceinline__ uint32_t su32(const void* p) {
    return (uint32_t)__cvta_generic_to_shared(p);
}
__device__ __forceinline__ uint32_t pack_bf16x2(float lo, float hi) {
    uint32_t r;
    asm("cvt.rn.bf16x2.f32 %0, %1, %2;" : "=r"(r) : "f"(hi), "f"(lo));
    return r;
}
// m16n8k16 bf16 HMMA, fp32 accumulate
#define MMA16816(c, a0, a1, a2, a3, b0, b1)                                   \
    asm volatile(                                                             \
        "mma.sync.aligned.m16n8k16.row.col.f32.bf16.bf16.f32 "                \
        "{%0,%1,%2,%3}, {%4,%5,%6,%7}, {%8,%9}, {%0,%1,%2,%3};"               \
        : "+f"((c)[0]), "+f"((c)[1]), "+f"((c)[2]), "+f"((c)[3])              \
        : "r"(a0), "r"(a1), "r"(a2), "r"(a3), "r"(b0), "r"(b1))

// ---------------- CSR build ----------------
__global__ void hist_bounds_k(const int* __restrict__ ei, int ne,
                              int* __restrict__ deg,
                              int* __restrict__ dr,
                              const int* __restrict__ batch,
                              int* __restrict__ nb,
                              const float* __restrict__ x,
                              __nv_bfloat162* __restrict__ xb) {
    int t = blockIdx.x * blockDim.x + threadIdx.x;
    if (t < ne) {
        int d = __ldg(&ei[ne + t]);
        int r = atomicAdd(&deg[d], 1);
        dr[t] = d | (r << 16);
    }
    if (t < N_NODES) {
        int b = __ldg(&batch[t]);
        if (t == 0) {
            for (int g = 0; g <= b; ++g) nb[g] = 0;
        } else {
            int p = __ldg(&batch[t - 1]);
            for (int g = p + 1; g <= b; ++g) nb[g] = t;
        }
        if (t == N_NODES - 1) {
            for (int g = b + 1; g <= N_GRAPHS; ++g) nb[g] = N_NODES;
        }
    }
    const float2* x2 = (const float2*)x;
    int stride = gridDim.x * blockDim.x;
    for (int i = t; i < N_NODES * DH / 2; i += stride) {
        float2 v = __ldg(&x2[i]);
        xb[i] = __float22bfloat162_rn(v);
    }
}

__global__ void s1_k(const int* __restrict__ deg, int* __restrict__ bsum) {
    __shared__ int red[1024];
    int n = blockIdx.x * 1024 + threadIdx.x;
    red[threadIdx.x] = (n < N_NODES) ? __ldg(&deg[n]) : 0;
    __syncthreads();
    #pragma unroll
    for (int s = 512; s > 0; s >>= 1) {
        if (threadIdx.x < s) red[threadIdx.x] += red[threadIdx.x + s];
        __syncthreads();
    }
    if (threadIdx.x == 0) bsum[blockIdx.x] = red[0];
}

__global__ void s3_k(const int* __restrict__ deg,
                     const int* __restrict__ bsum,
                     int* __restrict__ roff) {
    __shared__ int sv[1024];
    __shared__ int sb[64];
    __shared__ int bpref;
    int t = threadIdx.x;
    if (t < 64) sb[t] = (t < SCAN_BLOCKS && t < blockIdx.x) ? __ldg(&bsum[t]) : 0;
    __syncthreads();
    if (t < 32) {
        int v = sb[t] + sb[t + 32];
        #pragma unroll
        for (int o = 16; o > 0; o >>= 1)
            v += __shfl_down_sync(0xffffffffu, v, o);
        if (t == 0) bpref = v;
    }
    int n = blockIdx.x * 1024 + t;
    int dv = (n < N_NODES) ? __ldg(&deg[n]) : 0;
    sv[t] = dv;
    __syncthreads();
    #pragma unroll
    for (int o = 1; o < 1024; o <<= 1) {
        int u = (t >= o) ? sv[t - o] : 0;
        __syncthreads();
        sv[t] += u;
        __syncthreads();
    }
    if (n < N_NODES) roff[n] = bpref + sv[t] - dv;
    if (blockIdx.x == SCAN_BLOCKS - 1 && t == 1023)
        roff[N_NODES] = bpref + sv[1023];
}

// fill: atomic-free, reads packed dst|rank
__global__ void fill_k(const int* __restrict__ ei, int ne,
                       const int* __restrict__ roff,
                       const int* __restrict__ dr,
                       int* __restrict__ csr) {
    int t = blockIdx.x * blockDim.x + threadIdx.x;
    if (t < ne) {
        int pk = __ldg(&dr[t]);
        int d = pk & 0xFFFF;
        int r = pk >> 16;
        int s = __ldg(&ei[t]);
        csr[__ldg(&roff[d]) + r] = s;
    }
}

// ------- fused layer: bf16 gather + HMMA dual GEMM -------
#define A_STRIDE 272
#define A_BYTES (128 * A_STRIDE)
#define B_BYTES (64 * A_STRIDE)
#define LAYER_SMEM (A_BYTES + 2 * B_BYTES)   // 69632

__global__ __launch_bounds__(256, 3)
void layer_k(const uint4* __restrict__ Xb,
             const int* __restrict__ csr,
             const int* __restrict__ roff,
             const float* __restrict__ Wrel,
             const float* __restrict__ brel,
             const float* __restrict__ Wroot,
             uint32_t* __restrict__ outb,
             int do_relu) {
    extern __shared__ char sm[];
    __shared__ float s_bias[64];

    const unsigned FULL = 0xffffffffu;
    int tid = threadIdx.x;
    int warp = tid >> 5, lane = tid & 31;
    int rowBase = blockIdx.x * 128;

    uint32_t smA = su32(sm);
    uint32_t smBhi = smA + A_BYTES;
    uint32_t smBlo = smBhi + B_BYTES;

    if (tid < 64) s_bias[tid] = __ldg(&brel[tid]);

    // W stacked [Wrel;Wroot] -> Bt[n][k] hi/lo bf16
    for (int i = tid; i < 8192; i += 256) {
        int k = i >> 6, n = i & 63;
        float w = (k < 64) ? __ldg(&Wrel[k * 64 + n]) : __ldg(&Wroot[(k - 64) * 64 + n]);
        __nv_bfloat16 hi = __float2bfloat16_rn(w);
        __nv_bfloat16 lo = __float2bfloat16_rn(w - __bfloat162float(hi));
        uint32_t off = (uint32_t)(n * A_STRIDE + k * 2);
        asm volatile("st.shared.b16 [%0], %1;" :: "r"(smBhi + off), "h"(__bfloat16_as_ushort(hi)));
        asm volatile("st.shared.b16 [%0], %1;" :: "r"(smBlo + off), "h"(__bfloat16_as_ushort(lo)));
    }

    // x rows (bf16) -> A right half (cols 64..127)
    for (int i = tid; i < 1024; i += 256) {
        int r = i >> 3, c = i & 7;
        int g = rowBase + r;
        uint4 v = (g < N_NODES) ? __ldg(&Xb[(size_t)g * 8 + c])
                                : make_uint4(0, 0, 0, 0);
        uint32_t off = (uint32_t)(r * A_STRIDE + 128 + c * 16);
        asm volatile("st.shared.v4.b32 [%0], {%1,%2,%3,%4};"
                     :: "r"(smA + off), "r"(v.x), "r"(v.y), "r"(v.z), "r"(v.w));
    }

    // gather: 16 rows/warp -> A left half (cols 0..63)
    {
        int h = lane >> 3;
        int c = lane & 7;
        int rbase = rowBase + warp * 16;

        int off0 = 0;
        if (lane < 17) {
            int idx = rbase + lane;
            if (idx > N_NODES) idx = N_NODES;
            off0 = __ldg(&roff[idx]);
        }
        int j = __shfl_sync(FULL, off0, 0);
        int nxt = (lane < 16) ? __ldg(&csr[j + lane]) : 0;

        #pragma unroll 1
        for (int rr = 0; rr < 16; ++rr) {
            int end = __shfl_sync(FULL, off0, rr + 1);
            float a0 = 0.f, a1 = 0.f, a2 = 0.f, a3 = 0.f;
            float a4 = 0.f, a5 = 0.f, a6 = 0.f, a7 = 0.f;

            #pragma unroll 1
            while (j + 16 <= end) {
                int curI = nxt;
                nxt = (lane < 16) ? __ldg(&csr[j + 16 + lane]) : 0;
                int s0 = __shfl_sync(FULL, curI, 0 + h);
                int s1 = __shfl_sync(FULL, curI, 4 + h);
                int s2 = __shfl_sync(FULL, curI, 8 + h);
                int s3 = __shfl_sync(FULL, curI, 12 + h);
                uint4 v0 = __ldg(&Xb[(size_t)s0 * 8 + c]);
                uint4 v1 = __ldg(&Xb[(size_t)s1 * 8 + c]);
                uint4 v2 = __ldg(&Xb[(size_t)s2 * 8 + c]);
                uint4 v3 = __ldg(&Xb[(size_t)s3 * 8 + c]);
                ACC8(v0); ACC8(v1); ACC8(v2); ACC8(v3);
                j += 16;
            }
            int rem = end - j;   // 0..15
            if (rem > 0) {
                int curI = nxt;
                int q0 = 0;
                if (rem >= 8) {
                    int sa = __shfl_sync(FULL, curI, 0 + h);
                    int sb2 = __shfl_sync(FULL, curI, 4 + h);
                    uint4 va = __ldg(&Xb[(size_t)sa * 8 + c]);
                    uint4 vb = __ldg(&Xb[(size_t)sb2 * 8 + c]);
                    ACC8(va); ACC8(vb);
                    q0 = 8;
                }
                #pragma unroll
                for (int q = 0; q < 16; q += 4) {
                    if (q < q0) continue;
                    if (q >= rem) break;
                    int e = q + h;
                    bool valid = e < rem;
                    int s = __shfl_sync(FULL, curI, valid ? e : 0);
                    uint4 v = __ldg(&Xb[(size_t)s * 8 + c]);
                    if (valid) { ACC8(v); }
                }
                j = end;
                nxt = (lane < 16) ? __ldg(&csr[j + lane]) : 0;
            }
            #pragma unroll
            for (int o = 8; o <= 16; o <<= 1) {
                a0 += __shfl_xor_sync(FULL, a0, o);
                a1 += __shfl_xor_sync(FULL, a1, o);
                a2 += __shfl_xor_sync(FULL, a2, o);
                a3 += __shfl_xor_sync(FULL, a3, o);
                a4 += __shfl_xor_sync(FULL, a4, o);
                a5 += __shfl_xor_sync(FULL, a5, o);
                a6 += __shfl_xor_sync(FULL, a6, o);
                a7 += __shfl_xor_sync(FULL, a7, o);
            }
            if (lane < 8) {
                int r = warp * 16 + rr;
                uint32_t p0 = pack_bf16x2(a0, a1);
                uint32_t p1 = pack_bf16x2(a2, a3);
                uint32_t p2 = pack_bf16x2(a4, a5);
                uint32_t p3 = pack_bf16x2(a6, a7);
                uint32_t off = (uint32_t)(r * A_STRIDE + c * 16);
                asm volatile("st.shared.v4.b32 [%0], {%1,%2,%3,%4};"
                             :: "r"(smA + off), "r"(p0), "r"(p1), "r"(p2), "r"(p3));
            }
        }
    }
    __syncthreads();

    // HMMA: warp computes rows [warp*16, +16) x 64 cols
    float acc[8][4] = {};
    {
        uint32_t aBase = smA + (uint32_t)((warp * 16 + (lane >> 2)) * A_STRIDE + (lane & 3) * 4);
        uint32_t bBase = (uint32_t)((lane >> 2) * A_STRIDE + (lane & 3) * 4);
        #pragma unroll
        for (int k = 0; k < 8; ++k) {
            uint32_t ak = aBase + k * 32;
            uint32_t a0, a1, a2, a3;
            asm volatile("ld.shared.b32 %0, [%1];" : "=r"(a0) : "r"(ak));
            asm volatile("ld.shared.b32 %0, [%1];" : "=r"(a1) : "r"(ak + 8 * A_STRIDE));
            asm volatile("ld.shared.b32 %0, [%1];" : "=r"(a2) : "r"(ak + 16));
            asm volatile("ld.shared.b32 %0, [%1];" : "=r"(a3) : "r"(ak + 8 * A_STRIDE + 16));
            #pragma unroll
            for (int nf = 0; nf < 8; ++nf) {
                uint32_t bk = bBase + nf * (8 * A_STRIDE) + k * 32;
                uint32_t b0, b1;
                asm volatile("ld.shared.b32 %0, [%1];" : "=r"(b0) : "r"(smBhi + bk));
                asm volatile("ld.shared.b32 %0, [%1];" : "=r"(b1) : "r"(smBhi + bk + 16));
                MMA16816(acc[nf], a0, a1, a2, a3, b0, b1);
                asm volatile("ld.shared.b32 %0, [%1];" : "=r"(b0) : "r"(smBlo + bk));
                asm volatile("ld.shared.b32 %0, [%1];" : "=r"(b1) : "r"(smBlo + bk + 16));
                MMA16816(acc[nf], a0, a1, a2, a3, b0, b1);
            }
        }
    }

    // epilogue: bias + relu, bf16 stores
    {
        int r0 = rowBase + warp * 16 + (lane >> 2);
        int r1 = r0 + 8;
        int colq = (lane & 3) * 2;
        #pragma unroll
        for (int nf = 0; nf < 8; ++nf) {
            int cc = nf * 8 + colq;
            float b0 = s_bias[cc], b1 = s_bias[cc + 1];
            float o0 = acc[nf][0] + b0, o1 = acc[nf][1] + b1;
            float o2 = acc[nf][2] + b0, o3 = acc[nf][3] + b1;
            if (do_relu) {
                o0 = fmaxf(o0, 0.f); o1 = fmaxf(o1, 0.f);
                o2 = fmaxf(o2, 0.f); o3 = fmaxf(o3, 0.f);
            }
            if (r0 < N_NODES) outb[(size_t)r0 * 32 + (cc >> 1)] = pack_bf16x2(o0, o1);
            if (r1 < N_NODES) outb[(size_t)r1 * 32 + (cc >> 1)] = pack_bf16x2(o2, o3);
        }
    }
}

// ---- P1[g] = sum over edges of graph g of h2b[src] (8 parts per graph) ----
__global__ void p1_k(const uint4* __restrict__ Hb,
                     const int* __restrict__ csr,
                     const int* __restrict__ roff,
                     const int* __restrict__ nb,
                     float* __restrict__ P1) {
    int g = blockIdx.x >> 3, part = blockIdx.x & 7;
    int ns = __ldg(&nb[g]), neE = __ldg(&nb[g + 1]);
    int es = __ldg(&roff[ns]), ee = __ldg(&roff[neE]);
    long long len = ee - es;
    int start = es + (int)((len * part) >> 3);
    int end = es + (int)((len * (part + 1)) >> 3);
    int grp = threadIdx.x >> 3;
    int c = threadIdx.x & 7;
    float a0 = 0.f, a1 = 0.f, a2 = 0.f, a3 = 0.f;
    float a4 = 0.f, a5 = 0.f, a6 = 0.f, a7 = 0.f;
    int j = start + grp;
    for (; j + 32 < end; j += 64) {
        int s0 = __ldg(&csr[j]);
        int s1 = __ldg(&csr[j + 32]);
        uint4 v0 = __ldg(&Hb[(size_t)s0 * 8 + c]);
        uint4 v1 = __ldg(&Hb[(size_t)s1 * 8 + c]);
        ACC8(v0); ACC8(v1);
    }
    for (; j < end; j += 32) {
        int s0 = __ldg(&csr[j]);
        uint4 v0 = __ldg(&Hb[(size_t)s0 * 8 + c]);
        ACC8(v0);
    }
    __shared__ float sRed[32][72];
    *(float4*)&sRed[grp][c * 8]     = make_float4(a0, a1, a2, a3);
    *(float4*)&sRed[grp][c * 8 + 4] = make_float4(a4, a5, a6, a7);
    __syncthreads();
    if (threadIdx.x < 16) {
        int q = threadIdx.x;
        float4 s = make_float4(0.f, 0.f, 0.f, 0.f);
        #pragma unroll
        for (int t = 0; t < 32; ++t) {
            float4 v = *(float4*)&sRed[t][q * 4];
            s.x += v.x; s.y += v.y; s.z += v.z; s.w += v.w;
        }
        float* dst = P1 + g * DH + q * 4;
        asm volatile("red.global.add.v4.f32 [%0], {%1,%2,%3,%4};"
                     :: "l"(dst), "f"(s.x), "f"(s.y), "f"(s.z), "f"(s.w)
                     : "memory");
    }
}

// ---- finale (fused with P2 pooling): block g sums its node range, then GEMMs ----
__global__ void finale_k(const float* __restrict__ P1,
                         const uint4* __restrict__ Hb,
                         const int* __restrict__ nb,
                         const float* __restrict__ Wrel,
                         const float* __restrict__ brel,
                         const float* __restrict__ Wroot,
                         const float* __restrict__ Wlin,
                         const float* __restrict__ blin,
                         float* __restrict__ out) {
    __shared__ float sP2[64];
    __shared__ float st[64];
    __shared__ float sRed[32][72];
    int g = blockIdx.x;
    int s = __ldg(&nb[g]), e = __ldg(&nb[g + 1]);
    int tid = threadIdx.x;
    int grp = tid >> 3;
    int c = tid & 7;

    // P2 partial sums (pool2 logic inlined)
    {
        float a0 = 0.f, a1 = 0.f, a2 = 0.f, a3 = 0.f;
        float a4 = 0.f, a5 = 0.f, a6 = 0.f, a7 = 0.f;
        for (int r = s + grp; r < e; r += 32) {
            uint4 v = __ldg(&Hb[(size_t)r * 8 + c]);
            ACC8(v);
        }
        *(float4*)&sRed[grp][c * 8]     = make_float4(a0, a1, a2, a3);
        *(float4*)&sRed[grp][c * 8 + 4] = make_float4(a4, a5, a6, a7);
    }
    __syncthreads();
    if (tid < 16) {
        float4 sv = make_float4(0.f, 0.f, 0.f, 0.f);
        #pragma unroll
        for (int t = 0; t < 32; ++t) {
            float4 v = *(float4*)&sRed[t][tid * 4];
            sv.x += v.x; sv.y += v.y; sv.z += v.z; sv.w += v.w;
        }
        *(float4*)&sP2[tid * 4] = sv;
    }
    __syncthreads();

    // layer3-in-pooled-space GEMM (64 threads) then head (16 threads)
    if (tid < 64) {
        float cnt = fmaxf((float)(e - s), 1.0f);
        float t = 0.f;
        #pragma unroll 8
        for (int k = 0; k < 64; ++k)
            t += __ldg(&P1[g * DH + k]) * __ldg(&Wrel[k * DH + tid])
               + sP2[k] * __ldg(&Wroot[k * DH + tid]);
        st[tid] = t / cnt + __ldg(&brel[tid]);
    }
    __syncthreads();
    if (tid < DOUT) {
        float o = __ldg(&blin[tid]);
        #pragma unroll 8
        for (int k = 0; k < 64; ++k)
            o += st[k] * __ldg(&Wlin[k * DOUT + tid]);
        out[g * DOUT + tid] = o;
    }
}

extern "C" void kernel_launch(void* const* d_in, const int* in_sizes, int n_in,
                              void* d_out, int out_size) {
    const float* x      = (const float*)d_in[0];
    const int*   ei     = (const int*)d_in[1];
    const int*   batch  = (const int*)d_in[3];
    const float* Wrel1  = (const float*)d_in[4];
    const float* brel1  = (const float*)d_in[5];
    const float* Wroot1 = (const float*)d_in[6];
    const float* Wrel2  = (const float*)d_in[7];
    const float* brel2  = (const float*)d_in[8];
    const float* Wroot2 = (const float*)d_in[9];
    const float* Wrel3  = (const float*)d_in[10];
    const float* brel3  = (const float*)d_in[11];
    const float* Wroot3 = (const float*)d_in[12];
    const float* Wlin   = (const float*)d_in[13];
    const float* blin   = (const float*)d_in[14];
    float* out = (float*)d_out;

    int ne = in_sizes[1] / 2;

    void *xb_p, *h1b_p, *h2b_p, *deg_p, *roff_p, *dr_p, *csr_p,
         *p1_p, *nb_p, *bs_p;
    cudaGetSymbolAddress(&xb_p, g_xb);
    cudaGetSymbolAddress(&h1b_p, g_h1b);
    cudaGetSymbolAddress(&h2b_p, g_h2b);
    cudaGetSymbolAddress(&deg_p, g_deg);
    cudaGetSymbolAddress(&roff_p, g_roff);
    cudaGetSymbolAddress(&dr_p, g_dr);
    cudaGetSymbolAddress(&csr_p, g_csr);
    cudaGetSymbolAddress(&p1_p, g_P1);
    cudaGetSymbolAddress(&nb_p, g_nb);
    cudaGetSymbolAddress(&bs_p, g_bsum);

    uint4* xb = (uint4*)xb_p;
    uint4* h1b = (uint4*)h1b_p;
    uint4* h2b = (uint4*)h2b_p;
    int* deg = (int*)deg_p;
    int* roff = (int*)roff_p;
    int* dr = (int*)dr_p;
    int* csr = (int*)csr_p;
    float* P1 = (float*)p1_p;
    int* nb = (int*)nb_p;
    int* bsum = (int*)bs_p;

    static int attr_set = 0;
    if (!attr_set) {
        cudaFuncSetAttribute(layer_k,
                             cudaFuncAttributeMaxDynamicSharedMemorySize, LAYER_SMEM);
        attr_set = 1;
    }

    int edgeBlocks = (ne + 255) / 256;
    int layerBlocks = (N_NODES + 127) / 128;   // 391

    cudaMemsetAsync(deg, 0, N_NODES * sizeof(int), 0);
    hist_bounds_k<<<edgeBlocks, 256>>>(ei, ne, deg, dr, batch, nb, x,
                                       (__nv_bfloat162*)xb);
    s1_k<<<SCAN_BLOCKS, 1024>>>(deg, bsum);
    s3_k<<<SCAN_BLOCKS, 1024>>>(deg, bsum, roff);
    fill_k<<<edgeBlocks, 256>>>(ei, ne, roff, dr, csr);

    layer_k<<<layerBlocks, 256, LAYER_SMEM>>>(xb,  csr, roff, Wrel1, brel1, Wroot1,
                                              (uint32_t*)h1b, 1);
    layer_k<<<layerBlocks, 256, LAYER_SMEM>>>(h1b, csr, roff, Wrel2, brel2, Wroot2,
                                              (uint32_t*)h2b, 1);

    cudaMemsetAsync(P1, 0, N_GRAPHS * DH * sizeof(float), 0);
    p1_k<<<N_GRAPHS * 8, 256>>>(h2b, csr, roff, nb, P1);
    finale_k<<<N_GRAPHS, 256>>>(P1, h2b, nb, Wrel3, brel3, Wroot3, Wlin, blin, out);
}

// round 15
// speedup vs baseline: 1.3714x; 1.0277x over previous
#include <cuda_runtime.h>
#include <cuda_bf16.h>
#include <cstdint>

#define N_NODES 50000
#define N_GRAPHS 128
#define DH 64
#define DOUT 16
#define SCAN_BLOCKS 49
#define N_EDGES 1250000

// -------- static device scratch --------
__device__ uint4 g_xb[(size_t)N_NODES * 8];    // bf16 shadow (128B/row)
__device__ uint4 g_h1b[(size_t)N_NODES * 8];
__device__ uint4 g_h2b[(size_t)N_NODES * 8];
__device__ int   g_deg[N_NODES];               // zeroed by scan_k each pass
__device__ int   g_roff[N_NODES + 1];
__device__ int   g_dr[N_EDGES];                // packed dst | (rank<<16)
__device__ int   g_csr[N_EDGES + 32];
__device__ float g_P1[N_GRAPHS * DH];          // zeroed by finale_k each pass
__device__ int   g_nb[N_GRAPHS + 1];
__device__ int   g_pub[SCAN_BLOCKS];           // lookback: blockSum+1 (0 = not ready)

// unpack 8 bf16 (uint4) and accumulate into 8 fp32 (shift = exact bf16->f32)
#define ACC8(v)                                                         \
    do {                                                                \
        a0 += __uint_as_float((v).x << 16);                             \
        a1 += __uint_as_float((v).x & 0xffff0000u);                     \
        a2 += __uint_as_float((v).y << 16);                             \
        a3 += __uint_as_float((v).y & 0xffff0000u);                     \
        a4 += __uint_as_float((v).z << 16);                             \
        a5 += __uint_as_float((v).z & 0xffff0000u);                     \
        a6 += __uint_as_float((v).w << 16);                             \
        a7 += __uint_as_float((v).w & 0xffff0000u);                     \
    } while (0)

__device__ __forceinline__ uint32_t su32(const void* p) {
    return (uint32_t)__cvta_generic_to_shared(p);
}
__device__ __forceinline__ uint32_t pack_bf16x2(float lo, float hi) {
    uint32_t r;
    asm("cvt.rn.bf16x2.f32 %0, %1, %2;" : "=r"(r) : "f"(hi), "f"(lo));
    return r;
}
// m16n8k16 bf16 HMMA, fp32 accumulate
#define MMA16816(c, a0, a1, a2, a3, b0, b1)                                   \
    asm volatile(                                                             \
        "mma.sync.aligned.m16n8k16.row.col.f32.bf16.bf16.f32 "                \
        "{%0,%1,%2,%3}, {%4,%5,%6,%7}, {%8,%9}, {%0,%1,%2,%3};"               \
        : "+f"((c)[0]), "+f"((c)[1]), "+f"((c)[2]), "+f"((c)[3])              \
        : "r"(a0), "r"(a1), "r"(a2), "r"(a3), "r"(b0), "r"(b1))

// ---------------- CSR build ----------------
__global__ void hist_bounds_k(const int* __restrict__ ei, int ne,
                              int* __restrict__ deg,
                              int* __restrict__ dr,
                              const int* __restrict__ batch,
                              int* __restrict__ nb,
                              const float* __restrict__ x,
                              __nv_bfloat162* __restrict__ xb) {
    int t = blockIdx.x * blockDim.x + threadIdx.x;
    if (t < ne) {
        int d = __ldg(&ei[ne + t]);
        int r = atomicAdd(&deg[d], 1);
        dr[t] = d | (r << 16);
    }
    if (t < N_NODES) {
        int b = __ldg(&batch[t]);
        if (t == 0) {
            for (int g = 0; g <= b; ++g) nb[g] = 0;
        } else {
            int p = __ldg(&batch[t - 1]);
            for (int g = p + 1; g <= b; ++g) nb[g] = t;
        }
        if (t == N_NODES - 1) {
            for (int g = b + 1; g <= N_GRAPHS; ++g) nb[g] = N_NODES;
        }
    }
    const float2* x2 = (const float2*)x;
    int stride = gridDim.x * blockDim.x;
    for (int i = t; i < N_NODES * DH / 2; i += stride) {
        float2 v = __ldg(&x2[i]);
        xb[i] = __float22bfloat162_rn(v);
    }
}

// ---- single-pass scan with decoupled lookback; zeros deg for next replay ----
__global__ void scan_k(int* __restrict__ deg,
                       int* __restrict__ pub,
                       int* __restrict__ roff) {
    __shared__ int sv[1024];
    __shared__ int sred[64];
    __shared__ int bpref;
    int t = threadIdx.x;
    int bid = blockIdx.x;
    int n = bid * 1024 + t;
    int dv = (n < N_NODES) ? deg[n] : 0;
    sv[t] = dv;
    __syncthreads();
    // block-local inclusive scan
    #pragma unroll
    for (int o = 1; o < 1024; o <<= 1) {
        int u = (t >= o) ? sv[t - o] : 0;
        __syncthreads();
        sv[t] += u;
        __syncthreads();
    }
    // publish block sum (value+1 packs ready-flag into the word)
    if (t == 0) atomicExch(&pub[bid], sv[1023] + 1);

    // lookback: thread i (< bid) polls predecessor i
    int part = 0;
    if (t < bid) {
        int v;
        do { v = atomicAdd(&pub[t], 0); } while (v == 0);
        part = v - 1;
    }
    if (t < 64) sred[t] = 0;
    __syncthreads();
    // reduce up to 48 partials (bid <= 48): warp-reduce then combine
    if (t < 64) {
        int v = part;
        #pragma unroll
        for (int o = 16; o > 0; o >>= 1)
            v += __shfl_down_sync(0xffffffffu, v, o);
        if ((t & 31) == 0) sred[t >> 5] = v;
    }
    __syncthreads();
    if (t == 0) bpref = sred[0] + sred[1];
    __syncthreads();

    if (n < N_NODES) {
        roff[n] = bpref + sv[t] - dv;
        deg[n] = 0;                 // reset for next graph replay
    }
    if (bid == SCAN_BLOCKS - 1 && t == 1023)
        roff[N_NODES] = bpref + sv[1023];
}

// fill: atomic-free, reads packed dst|rank; block 0 resets lookback words
__global__ void fill_k(const int* __restrict__ ei, int ne,
                       const int* __restrict__ roff,
                       const int* __restrict__ dr,
                       int* __restrict__ csr,
                       int* __restrict__ pub) {
    int t = blockIdx.x * blockDim.x + threadIdx.x;
    if (blockIdx.x == 0 && threadIdx.x < SCAN_BLOCKS)
        pub[threadIdx.x] = 0;       // for next replay (scan already consumed)
    if (t < ne) {
        int pk = __ldg(&dr[t]);
        int d = pk & 0xFFFF;
        int r = pk >> 16;
        int s = __ldg(&ei[t]);
        csr[__ldg(&roff[d]) + r] = s;
    }
}

// ------- fused layer: bf16 gather + HMMA dual GEMM -------
#define A_STRIDE 272
#define A_BYTES (128 * A_STRIDE)
#define B_BYTES (64 * A_STRIDE)
#define LAYER_SMEM (A_BYTES + 2 * B_BYTES)   // 69632

__global__ __launch_bounds__(256, 3)
void layer_k(const uint4* __restrict__ Xb,
             const int* __restrict__ csr,
             const int* __restrict__ roff,
             const float* __restrict__ Wrel,
             const float* __restrict__ brel,
             const float* __restrict__ Wroot,
             uint32_t* __restrict__ outb,
             int do_relu) {
    extern __shared__ char sm[];
    __shared__ float s_bias[64];

    const unsigned FULL = 0xffffffffu;
    int tid = threadIdx.x;
    int warp = tid >> 5, lane = tid & 31;
    int rowBase = blockIdx.x * 128;

    uint32_t smA = su32(sm);
    uint32_t smBhi = smA + A_BYTES;
    uint32_t smBlo = smBhi + B_BYTES;

    if (tid < 64) s_bias[tid] = __ldg(&brel[tid]);

    // W stacked [Wrel;Wroot] -> Bt[n][k] hi/lo bf16
    for (int i = tid; i < 8192; i += 256) {
        int k = i >> 6, n = i & 63;
        float w = (k < 64) ? __ldg(&Wrel[k * 64 + n]) : __ldg(&Wroot[(k - 64) * 64 + n]);
        __nv_bfloat16 hi = __float2bfloat16_rn(w);
        __nv_bfloat16 lo = __float2bfloat16_rn(w - __bfloat162float(hi));
        uint32_t off = (uint32_t)(n * A_STRIDE + k * 2);
        asm volatile("st.shared.b16 [%0], %1;" :: "r"(smBhi + off), "h"(__bfloat16_as_ushort(hi)));
        asm volatile("st.shared.b16 [%0], %1;" :: "r"(smBlo + off), "h"(__bfloat16_as_ushort(lo)));
    }

    // x rows (bf16) -> A right half (cols 64..127)
    for (int i = tid; i < 1024; i += 256) {
        int r = i >> 3, c = i & 7;
        int g = rowBase + r;
        uint4 v = (g < N_NODES) ? __ldg(&Xb[(size_t)g * 8 + c])
                                : make_uint4(0, 0, 0, 0);
        uint32_t off = (uint32_t)(r * A_STRIDE + 128 + c * 16);
        asm volatile("st.shared.v4.b32 [%0], {%1,%2,%3,%4};"
                     :: "r"(smA + off), "r"(v.x), "r"(v.y), "r"(v.z), "r"(v.w));
    }

    // gather: 16 rows/warp -> A left half (cols 0..63)
    {
        int h = lane >> 3;
        int c = lane & 7;
        int rbase = rowBase + warp * 16;

        int off0 = 0;
        if (lane < 17) {
            int idx = rbase + lane;
            if (idx > N_NODES) idx = N_NODES;
            off0 = __ldg(&roff[idx]);
        }
        int j = __shfl_sync(FULL, off0, 0);
        int nxt = (lane < 16) ? __ldg(&csr[j + lane]) : 0;

        #pragma unroll 1
        for (int rr = 0; rr < 16; ++rr) {
            int end = __shfl_sync(FULL, off0, rr + 1);
            float a0 = 0.f, a1 = 0.f, a2 = 0.f, a3 = 0.f;
            float a4 = 0.f, a5 = 0.f, a6 = 0.f, a7 = 0.f;

            #pragma unroll 1
            while (j + 16 <= end) {
                int curI = nxt;
                nxt = (lane < 16) ? __ldg(&csr[j + 16 + lane]) : 0;
                int s0 = __shfl_sync(FULL, curI, 0 + h);
                int s1 = __shfl_sync(FULL, curI, 4 + h);
                int s2 = __shfl_sync(FULL, curI, 8 + h);
                int s3 = __shfl_sync(FULL, curI, 12 + h);
                uint4 v0 = __ldg(&Xb[(size_t)s0 * 8 + c]);
                uint4 v1 = __ldg(&Xb[(size_t)s1 * 8 + c]);
                uint4 v2 = __ldg(&Xb[(size_t)s2 * 8 + c]);
                uint4 v3 = __ldg(&Xb[(size_t)s3 * 8 + c]);
                ACC8(v0); ACC8(v1); ACC8(v2); ACC8(v3);
                j += 16;
            }
            int rem = end - j;   // 0..15
            if (rem > 0) {
                int curI = nxt;
                int q0 = 0;
                if (rem >= 8) {
                    int sa = __shfl_sync(FULL, curI, 0 + h);
                    int sb2 = __shfl_sync(FULL, curI, 4 + h);
                    uint4 va = __ldg(&Xb[(size_t)sa * 8 + c]);
                    uint4 vb = __ldg(&Xb[(size_t)sb2 * 8 + c]);
                    ACC8(va); ACC8(vb);
                    q0 = 8;
                }
                #pragma unroll
                for (int q = 0; q < 16; q += 4) {
                    if (q < q0) continue;
                    if (q >= rem) break;
                    int e = q + h;
                    bool valid = e < rem;
                    int s = __shfl_sync(FULL, curI, valid ? e : 0);
                    uint4 v = __ldg(&Xb[(size_t)s * 8 + c]);
                    if (valid) { ACC8(v); }
                }
                j = end;
                nxt = (lane < 16) ? __ldg(&csr[j + lane]) : 0;
            }
            #pragma unroll
            for (int o = 8; o <= 16; o <<= 1) {
                a0 += __shfl_xor_sync(FULL, a0, o);
                a1 += __shfl_xor_sync(FULL, a1, o);
                a2 += __shfl_xor_sync(FULL, a2, o);
                a3 += __shfl_xor_sync(FULL, a3, o);
                a4 += __shfl_xor_sync(FULL, a4, o);
                a5 += __shfl_xor_sync(FULL, a5, o);
                a6 += __shfl_xor_sync(FULL, a6, o);
                a7 += __shfl_xor_sync(FULL, a7, o);
            }
            if (lane < 8) {
                int r = warp * 16 + rr;
                uint32_t p0 = pack_bf16x2(a0, a1);
                uint32_t p1 = pack_bf16x2(a2, a3);
                uint32_t p2 = pack_bf16x2(a4, a5);
                uint32_t p3 = pack_bf16x2(a6, a7);
                uint32_t off = (uint32_t)(r * A_STRIDE + c * 16);
                asm volatile("st.shared.v4.b32 [%0], {%1,%2,%3,%4};"
                             :: "r"(smA + off), "r"(p0), "r"(p1), "r"(p2), "r"(p3));
            }
        }
    }
    __syncthreads();

    // HMMA: warp computes rows [warp*16, +16) x 64 cols
    float acc[8][4] = {};
    {
        uint32_t aBase = smA + (uint32_t)((warp * 16 + (lane >> 2)) * A_STRIDE + (lane & 3) * 4);
        uint32_t bBase = (uint32_t)((lane >> 2) * A_STRIDE + (lane & 3) * 4);
        #pragma unroll
        for (int k = 0; k < 8; ++k) {
            uint32_t ak = aBase + k * 32;
            uint32_t a0, a1, a2, a3;
            asm volatile("ld.shared.b32 %0, [%1];" : "=r"(a0) : "r"(ak));
            asm volatile("ld.shared.b32 %0, [%1];" : "=r"(a1) : "r"(ak + 8 * A_STRIDE));
            asm volatile("ld.shared.b32 %0, [%1];" : "=r"(a2) : "r"(ak + 16));
            asm volatile("ld.shared.b32 %0, [%1];" : "=r"(a3) : "r"(ak + 8 * A_STRIDE + 16));
            #pragma unroll
            for (int nf = 0; nf < 8; ++nf) {
                uint32_t bk = bBase + nf * (8 * A_STRIDE) + k * 32;
                uint32_t b0, b1;
                asm volatile("ld.shared.b32 %0, [%1];" : "=r"(b0) : "r"(smBhi + bk));
                asm volatile("ld.shared.b32 %0, [%1];" : "=r"(b1) : "r"(smBhi + bk + 16));
                MMA16816(acc[nf], a0, a1, a2, a3, b0, b1);
                asm volatile("ld.shared.b32 %0, [%1];" : "=r"(b0) : "r"(smBlo + bk));
                asm volatile("ld.shared.b32 %0, [%1];" : "=r"(b1) : "r"(smBlo + bk + 16));
                MMA16816(acc[nf], a0, a1, a2, a3, b0, b1);
            }
        }
    }

    // epilogue: bias + relu, bf16 stores
    {
        int r0 = rowBase + warp * 16 + (lane >> 2);
        int r1 = r0 + 8;
        int colq = (lane & 3) * 2;
        #pragma unroll
        for (int nf = 0; nf < 8; ++nf) {
            int cc = nf * 8 + colq;
            float b0 = s_bias[cc], b1 = s_bias[cc + 1];
            float o0 = acc[nf][0] + b0, o1 = acc[nf][1] + b1;
            float o2 = acc[nf][2] + b0, o3 = acc[nf][3] + b1;
            if (do_relu) {
                o0 = fmaxf(o0, 0.f); o1 = fmaxf(o1, 0.f);
                o2 = fmaxf(o2, 0.f); o3 = fmaxf(o3, 0.f);
            }
            if (r0 < N_NODES) outb[(size_t)r0 * 32 + (cc >> 1)] = pack_bf16x2(o0, o1);
            if (r1 < N_NODES) outb[(size_t)r1 * 32 + (cc >> 1)] = pack_bf16x2(o2, o3);
        }
    }
}

// ---- P1[g] = sum over edges of graph g of h2b[src] (8 parts per graph) ----
__global__ void p1_k(const uint4* __restrict__ Hb,
                     const int* __restrict__ csr,
                     const int* __restrict__ roff,
                     const int* __restrict__ nb,
                     float* __restrict__ P1) {
    int g = blockIdx.x >> 3, part = blockIdx.x & 7;
    int ns = __ldg(&nb[g]), neE = __ldg(&nb[g + 1]);
    int es = __ldg(&roff[ns]), ee = __ldg(&roff[neE]);
    long long len = ee - es;
    int start = es + (int)((len * part) >> 3);
    int end = es + (int)((len * (part + 1)) >> 3);
    int grp = threadIdx.x >> 3;
    int c = threadIdx.x & 7;
    float a0 = 0.f, a1 = 0.f, a2 = 0.f, a3 = 0.f;
    float a4 = 0.f, a5 = 0.f, a6 = 0.f, a7 = 0.f;
    int j = start + grp;
    for (; j + 32 < end; j += 64) {
        int s0 = __ldg(&csr[j]);
        int s1 = __ldg(&csr[j + 32]);
        uint4 v0 = __ldg(&Hb[(size_t)s0 * 8 + c]);
        uint4 v1 = __ldg(&Hb[(size_t)s1 * 8 + c]);
        ACC8(v0); ACC8(v1);
    }
    for (; j < end; j += 32) {
        int s0 = __ldg(&csr[j]);
        uint4 v0 = __ldg(&Hb[(size_t)s0 * 8 + c]);
        ACC8(v0);
    }
    __shared__ float sRed[32][72];
    *(float4*)&sRed[grp][c * 8]     = make_float4(a0, a1, a2, a3);
    *(float4*)&sRed[grp][c * 8 + 4] = make_float4(a4, a5, a6, a7);
    __syncthreads();
    if (threadIdx.x < 16) {
        int q = threadIdx.x;
        float4 s = make_float4(0.f, 0.f, 0.f, 0.f);
        #pragma unroll
        for (int t = 0; t < 32; ++t) {
            float4 v = *(float4*)&sRed[t][q * 4];
            s.x += v.x; s.y += v.y; s.z += v.z; s.w += v.w;
        }
        float* dst = P1 + g * DH + q * 4;
        asm volatile("red.global.add.v4.f32 [%0], {%1,%2,%3,%4};"
                     :: "l"(dst), "f"(s.x), "f"(s.y), "f"(s.z), "f"(s.w)
                     : "memory");
    }
}

// ---- finale (fused P2 pooling + GEMMs); zeros P1 for next replay ----
__global__ void finale_k(float* __restrict__ P1,
                         const uint4* __restrict__ Hb,
                         const int* __restrict__ nb,
                         const float* __restrict__ Wrel,
                         const float* __restrict__ brel,
                         const float* __restrict__ Wroot,
                         const float* __restrict__ Wlin,
                         const float* __restrict__ blin,
                         float* __restrict__ out) {
    __shared__ float sP2[64];
    __shared__ float sP1[64];
    __shared__ float st[64];
    __shared__ float sRed[32][72];
    int g = blockIdx.x;
    int s = __ldg(&nb[g]), e = __ldg(&nb[g + 1]);
    int tid = threadIdx.x;
    int grp = tid >> 3;
    int c = tid & 7;

    if (tid < 64) sP1[tid] = P1[g * DH + tid];

    // P2 partial sums
    {
        float a0 = 0.f, a1 = 0.f, a2 = 0.f, a3 = 0.f;
        float a4 = 0.f, a5 = 0.f, a6 = 0.f, a7 = 0.f;
        for (int r = s + grp; r < e; r += 32) {
            uint4 v = __ldg(&Hb[(size_t)r * 8 + c]);
            ACC8(v);
        }
        *(float4*)&sRed[grp][c * 8]     = make_float4(a0, a1, a2, a3);
        *(float4*)&sRed[grp][c * 8 + 4] = make_float4(a4, a5, a6, a7);
    }
    __syncthreads();
    if (tid < 16) {
        float4 sv = make_float4(0.f, 0.f, 0.f, 0.f);
        #pragma unroll
        for (int t = 0; t < 32; ++t) {
            float4 v = *(float4*)&sRed[t][tid * 4];
            sv.x += v.x; sv.y += v.y; sv.z += v.z; sv.w += v.w;
        }
        *(float4*)&sP2[tid * 4] = sv;
    }
    __syncthreads();

    // layer3-in-pooled-space GEMM (64 threads) then head (16 threads)
    if (tid < 64) {
        float cnt = fmaxf((float)(e - s), 1.0f);
        float t = 0.f;
        #pragma unroll 8
        for (int k = 0; k < 64; ++k)
            t += sP1[k] * __ldg(&Wrel[k * DH + tid])
               + sP2[k] * __ldg(&Wroot[k * DH + tid]);
        st[tid] = t / cnt + __ldg(&brel[tid]);
        P1[g * DH + tid] = 0.0f;    // reset for next graph replay
    }
    __syncthreads();
    if (tid < DOUT) {
        float o = __ldg(&blin[tid]);
        #pragma unroll 8
        for (int k = 0; k < 64; ++k)
            o += st[k] * __ldg(&Wlin[k * DOUT + tid]);
        out[g * DOUT + tid] = o;
    }
}

extern "C" void kernel_launch(void* const* d_in, const int* in_sizes, int n_in,
                              void* d_out, int out_size) {
    const float* x      = (const float*)d_in[0];
    const int*   ei     = (const int*)d_in[1];
    const int*   batch  = (const int*)d_in[3];
    const float* Wrel1  = (const float*)d_in[4];
    const float* brel1  = (const float*)d_in[5];
    const float* Wroot1 = (const float*)d_in[6];
    const float* Wrel2  = (const float*)d_in[7];
    const float* brel2  = (const float*)d_in[8];
    const float* Wroot2 = (const float*)d_in[9];
    const float* Wrel3  = (const float*)d_in[10];
    const float* brel3  = (const float*)d_in[11];
    const float* Wroot3 = (const float*)d_in[12];
    const float* Wlin   = (const float*)d_in[13];
    const float* blin   = (const float*)d_in[14];
    float* out = (float*)d_out;

    int ne = in_sizes[1] / 2;

    void *xb_p, *h1b_p, *h2b_p, *deg_p, *roff_p, *dr_p, *csr_p,
         *p1_p, *nb_p, *pub_p;
    cudaGetSymbolAddress(&xb_p, g_xb);
    cudaGetSymbolAddress(&h1b_p, g_h1b);
    cudaGetSymbolAddress(&h2b_p, g_h2b);
    cudaGetSymbolAddress(&deg_p, g_deg);
    cudaGetSymbolAddress(&roff_p, g_roff);
    cudaGetSymbolAddress(&dr_p, g_dr);
    cudaGetSymbolAddress(&csr_p, g_csr);
    cudaGetSymbolAddress(&p1_p, g_P1);
    cudaGetSymbolAddress(&nb_p, g_nb);
    cudaGetSymbolAddress(&pub_p, g_pub);

    uint4* xb = (uint4*)xb_p;
    uint4* h1b = (uint4*)h1b_p;
    uint4* h2b = (uint4*)h2b_p;
    int* deg = (int*)deg_p;
    int* roff = (int*)roff_p;
    int* dr = (int*)dr_p;
    int* csr = (int*)csr_p;
    float* P1 = (float*)p1_p;
    int* nb = (int*)nb_p;
    int* pub = (int*)pub_p;

    static int attr_set = 0;
    if (!attr_set) {
        cudaFuncSetAttribute(layer_k,
                             cudaFuncAttributeMaxDynamicSharedMemorySize, LAYER_SMEM);
        attr_set = 1;
    }

    int edgeBlocks = (ne + 255) / 256;
    int layerBlocks = (N_NODES + 127) / 128;   // 391

    // 7-launch pipeline (deg/P1/pub resets folded into consumers)
    hist_bounds_k<<<edgeBlocks, 256>>>(ei, ne, deg, dr, batch, nb, x,
                                       (__nv_bfloat162*)xb);
    scan_k<<<SCAN_BLOCKS, 1024>>>(deg, pub, roff);
    fill_k<<<edgeBlocks, 256>>>(ei, ne, roff, dr, csr, pub);

    layer_k<<<layerBlocks, 256, LAYER_SMEM>>>(xb,  csr, roff, Wrel1, brel1, Wroot1,
                                              (uint32_t*)h1b, 1);
    layer_k<<<layerBlocks, 256, LAYER_SMEM>>>(h1b, csr, roff, Wrel2, brel2, Wroot2,
                                              (uint32_t*)h2b, 1);

    p1_k<<<N_GRAPHS * 8, 256>>>(h2b, csr, roff, nb, P1);
    finale_k<<<N_GRAPHS, 256>>>(P1, h2b, nb, Wrel3, brel3, Wroot3, Wlin, blin, out);
}